// round 3
// baseline (speedup 1.0000x reference)
#include <cuda_runtime.h>

#define BB 512   // batch
#define TT 256   // seq len
#define HH 64    // hidden
#define GG 256   // 4*H gates
#define DD 64    // input/output dim

// Scratch (static __device__ arrays — allocation-free per harness rules)
__device__ float g_xg[(size_t)TT * BB * GG];   // gate pre-activations [T][B][G]
__device__ float g_hseq[(size_t)TT * BB * HH]; // hidden sequence [T][B][H]
__device__ float g_lat[BB * HH];               // encoder latent [B][H]
__device__ float g_xgc[BB * GG];               // dec0 constant xg [B][G]

typedef unsigned long long u64;

__device__ __forceinline__ u64 ffma2(u64 a, u64 b, u64 c) {
    u64 d;
    asm("fma.rn.f32x2 %0, %1, %2, %3;" : "=l"(d) : "l"(a), "l"(b), "l"(c));
    return d;
}
__device__ __forceinline__ float2 up2(u64 v) {
    float lo, hi;
    asm("mov.b64 {%0, %1}, %2;" : "=f"(lo), "=f"(hi) : "l"(v));
    return make_float2(lo, hi);
}

__device__ __forceinline__ float fsigm(float x) {
    return __fdividef(1.0f, 1.0f + __expf(-x));
}
__device__ __forceinline__ float ftanh(float x) {
    return 1.0f - __fdividef(2.0f, __expf(2.0f * x) + 1.0f);
}

// ---------------------------------------------------------------------------
// xg GEMM: out[n][g] = sum_k X[b(n),t(n)][k] * W[g][k] + bih[g] + bhh[g]
// n = t*BB + b. X element offset = b*st_b + t*st_t + k. K = 64 fixed.
// ---------------------------------------------------------------------------
__global__ __launch_bounds__(256) void xg_gemm(
    const float* __restrict__ X, int st_b, int st_t,
    const float* __restrict__ W,
    const float* __restrict__ bih, const float* __restrict__ bhh,
    float* __restrict__ out)
{
    __shared__ float Xs[64][128];  // [k][m]
    __shared__ float Ws[64][64];   // [k][g]
    const int tid  = threadIdx.x;
    const int row0 = blockIdx.x * 128;
    const int col0 = blockIdx.y * 64;

    #pragma unroll
    for (int i = 0; i < 8; i++) {
        int idx = tid + i * 256;
        int m   = idx & 127;
        int k4  = idx >> 7;
        int n   = row0 + m;
        int b   = n & (BB - 1);
        int t   = n >> 9;
        float4 v = *(const float4*)(X + (size_t)b * st_b + (size_t)t * st_t + k4 * 4);
        Xs[k4*4+0][m] = v.x; Xs[k4*4+1][m] = v.y;
        Xs[k4*4+2][m] = v.z; Xs[k4*4+3][m] = v.w;
    }
    #pragma unroll
    for (int i = 0; i < 4; i++) {
        int idx = tid + i * 256;
        int m   = idx & 63;
        int k4  = idx >> 6;
        float4 v = *(const float4*)(W + (size_t)(col0 + m) * 64 + k4 * 4);
        Ws[k4*4+0][m] = v.x; Ws[k4*4+1][m] = v.y;
        Ws[k4*4+2][m] = v.z; Ws[k4*4+3][m] = v.w;
    }
    __syncthreads();

    const int tx = tid & 15;
    const int ty = tid >> 4;

    float4 bi = *(const float4*)(bih + col0 + tx * 4);
    float4 bh = *(const float4*)(bhh + col0 + tx * 4);
    const float bs0 = bi.x + bh.x, bs1 = bi.y + bh.y;
    const float bs2 = bi.z + bh.z, bs3 = bi.w + bh.w;

    float acc[8][4];
    #pragma unroll
    for (int r = 0; r < 8; r++) {
        acc[r][0] = bs0; acc[r][1] = bs1; acc[r][2] = bs2; acc[r][3] = bs3;
    }

    #pragma unroll 16
    for (int k = 0; k < 64; k++) {
        float4 a0 = *(const float4*)&Xs[k][ty * 8];
        float4 a1 = *(const float4*)&Xs[k][ty * 8 + 4];
        float4 wv = *(const float4*)&Ws[k][tx * 4];
        float a[8] = {a0.x, a0.y, a0.z, a0.w, a1.x, a1.y, a1.z, a1.w};
        #pragma unroll
        for (int r = 0; r < 8; r++) {
            acc[r][0] = fmaf(a[r], wv.x, acc[r][0]);
            acc[r][1] = fmaf(a[r], wv.y, acc[r][1]);
            acc[r][2] = fmaf(a[r], wv.z, acc[r][2]);
            acc[r][3] = fmaf(a[r], wv.w, acc[r][3]);
        }
    }
    #pragma unroll
    for (int r = 0; r < 8; r++) {
        float4 o = make_float4(acc[r][0], acc[r][1], acc[r][2], acc[r][3]);
        *(float4*)(out + (size_t)(row0 + ty * 8 + r) * GG + col0 + tx * 4) = o;
    }
}

// ---------------------------------------------------------------------------
// FC GEMM: out[b][t][d] = hseq_row(n=t*BB+b) . fcW[d] + fcb[d]
// ---------------------------------------------------------------------------
__global__ __launch_bounds__(256) void fc_gemm(
    const float* __restrict__ X,
    const float* __restrict__ W,
    const float* __restrict__ bias,
    float* __restrict__ out)
{
    __shared__ float Xs[64][128];
    __shared__ float Ws[64][64];
    const int tid  = threadIdx.x;
    const int row0 = blockIdx.x * 128;

    #pragma unroll
    for (int i = 0; i < 8; i++) {
        int idx = tid + i * 256;
        int m   = idx & 127;
        int k4  = idx >> 7;
        float4 v = *(const float4*)(X + (size_t)(row0 + m) * 64 + k4 * 4);
        Xs[k4*4+0][m] = v.x; Xs[k4*4+1][m] = v.y;
        Xs[k4*4+2][m] = v.z; Xs[k4*4+3][m] = v.w;
    }
    #pragma unroll
    for (int i = 0; i < 4; i++) {
        int idx = tid + i * 256;
        int m   = idx & 63;
        int k4  = idx >> 6;
        float4 v = *(const float4*)(W + (size_t)m * 64 + k4 * 4);
        Ws[k4*4+0][m] = v.x; Ws[k4*4+1][m] = v.y;
        Ws[k4*4+2][m] = v.z; Ws[k4*4+3][m] = v.w;
    }
    __syncthreads();

    const int tx = tid & 15;
    const int ty = tid >> 4;

    float4 bv = *(const float4*)(bias + tx * 4);
    float acc[8][4];
    #pragma unroll
    for (int r = 0; r < 8; r++) {
        acc[r][0] = bv.x; acc[r][1] = bv.y; acc[r][2] = bv.z; acc[r][3] = bv.w;
    }

    #pragma unroll 16
    for (int k = 0; k < 64; k++) {
        float4 a0 = *(const float4*)&Xs[k][ty * 8];
        float4 a1 = *(const float4*)&Xs[k][ty * 8 + 4];
        float4 wv = *(const float4*)&Ws[k][tx * 4];
        float a[8] = {a0.x, a0.y, a0.z, a0.w, a1.x, a1.y, a1.z, a1.w};
        #pragma unroll
        for (int r = 0; r < 8; r++) {
            acc[r][0] = fmaf(a[r], wv.x, acc[r][0]);
            acc[r][1] = fmaf(a[r], wv.y, acc[r][1]);
            acc[r][2] = fmaf(a[r], wv.z, acc[r][2]);
            acc[r][3] = fmaf(a[r], wv.w, acc[r][3]);
        }
    }
    #pragma unroll
    for (int r = 0; r < 8; r++) {
        int n = row0 + ty * 8 + r;
        int b = n & (BB - 1);
        int t = n >> 9;
        float4 o = make_float4(acc[r][0], acc[r][1], acc[r][2], acc[r][3]);
        *(float4*)(out + ((size_t)b * TT + t) * DD + tx * 4) = o;
    }
}

// ---------------------------------------------------------------------------
// LSTM recurrence scan, unit-owner layout, ONE barrier per step.
// Block = 256 threads = 4 batch elements. Thread t:
//   bp  = t>>7       : batch pair (0/1) -> batches {2bp, 2bp+1}
//   par = t&1        : k-half for the dot phase; batch parity for finish phase
//   j   = (t>>1)&63  : hidden unit
// Dot phase: thread accumulates 4-gate partial dots over k in
// [32*par, 32*par+32) for BOTH batches of its pair (weights: 64 u64 regs).
// Combine: shfl_xor(1) swaps the cross-(half,batch) partials so that after
// one shuffle per gate, lane parity holds the FULL 4 gate sums for batch
// 2bp+par. Finish: activations + cell update thread-local (c in register),
// h written to a double-buffered shared array -> single __syncthreads.
// h rows padded to 40 floats so the two k-half read streams are bank-disjoint.
// XGC: xg constant over time (dec0). SMODE: 0 = full hseq, 1 = last h only.
// ---------------------------------------------------------------------------
template<int XGC, int SMODE>
__global__ __launch_bounds__(256, 1) void lstm_scan(
    const float* __restrict__ xg,
    const float* __restrict__ Whh,
    float* __restrict__ hout)
{
    // [buf][batch-in-block][k-half][40 floats: 32 used + 8 pad]
    __shared__ float h_sh[2][4][2][40];

    const int tid = threadIdx.x;
    const int bp  = tid >> 7;
    const int par = tid & 1;
    const int j   = (tid >> 1) & 63;
    const int bA  = 2 * bp;               // local batch pair base
    const int b0  = blockIdx.x * 4;       // global batch base
    const int bfin = b0 + bA + par;       // global batch this thread finishes

    // Weights: 4 gate rows at unit j, k in [32*par, 32*par+32), packed pairs.
    u64 w2[4][16];
    #pragma unroll
    for (int g = 0; g < 4; g++) {
        const ulonglong2* wp =
            (const ulonglong2*)(Whh + (size_t)(g * 64 + j) * 64 + 32 * par);
        #pragma unroll
        for (int i = 0; i < 8; i++) {
            ulonglong2 v = wp[i];
            w2[g][2 * i] = v.x; w2[g][2 * i + 1] = v.y;
        }
    }

    // Zero initial h buffer (buf 0), incl. padding
    for (int idx = tid; idx < 4 * 2 * 40; idx += 256)
        ((float*)h_sh[0])[idx] = 0.f;

    // xg for t=0 for the batch/unit this thread finishes
    float xge[4];
    {
        const float* p = xg + (size_t)bfin * GG + j;
        #pragma unroll
        for (int g = 0; g < 4; g++) xge[g] = p[g * 64];
    }
    float c = 0.f;
    __syncthreads();

    for (int t = 0; t < TT; t++) {
        float cur[4];
        #pragma unroll
        for (int g = 0; g < 4; g++) cur[g] = xge[g];
        if (!XGC && t + 1 < TT) {  // prefetch next step's xg
            const float* p = xg + ((size_t)(t + 1) * BB + bfin) * GG + j;
            #pragma unroll
            for (int g = 0; g < 4; g++) xge[g] = p[g * 64];
        }

        // Partial dots for both batches of the pair over this thread's k-half
        u64 acc0[4] = {0ull, 0ull, 0ull, 0ull};
        u64 acc1[4] = {0ull, 0ull, 0ull, 0ull};
        const ulonglong2* hb0 = (const ulonglong2*)&h_sh[t & 1][bA][par][0];
        const ulonglong2* hb1 = (const ulonglong2*)&h_sh[t & 1][bA + 1][par][0];
        #pragma unroll
        for (int i = 0; i < 8; i++) {
            ulonglong2 q0 = hb0[i];
            ulonglong2 q1 = hb1[i];
            #pragma unroll
            for (int g = 0; g < 4; g++) {
                acc0[g] = ffma2(q0.x, w2[g][2 * i],     acc0[g]);
                acc0[g] = ffma2(q0.y, w2[g][2 * i + 1], acc0[g]);
                acc1[g] = ffma2(q1.x, w2[g][2 * i],     acc1[g]);
                acc1[g] = ffma2(q1.y, w2[g][2 * i + 1], acc1[g]);
            }
        }

        // Fold packed lanes, exchange cross partials, finish batch (bA+par)
        float tot[4];
        #pragma unroll
        for (int g = 0; g < 4; g++) {
            float2 p0 = up2(acc0[g]);
            float2 p1 = up2(acc1[g]);
            float s0 = p0.x + p0.y;       // partial: batch bA,   my k-half
            float s1 = p1.x + p1.y;       // partial: batch bA+1, my k-half
            float send = par ? s0 : s1;   // partial of the OTHER lane's batch
            float mine = par ? s1 : s0;   // partial of MY batch
            float other = __shfl_xor_sync(0xFFFFFFFFu, send, 1);
            tot[g] = (mine + other) + cur[g];
        }

        float gi = fsigm(tot[0]);
        float gf = fsigm(tot[1]);
        float gc = ftanh(tot[2]);
        float go = fsigm(tot[3]);
        c = fmaf(gf, c, gi * gc);
        float h = go * ftanh(c);

        h_sh[(t + 1) & 1][bA + par][j >> 5][j & 31] = h;
        if (SMODE == 0)
            hout[((size_t)t * BB + bfin) * HH + j] = h;
        if (SMODE == 1 && t == TT - 1)
            hout[(size_t)bfin * HH + j] = h;
        __syncthreads();
    }
}

// ---------------------------------------------------------------------------
extern "C" void kernel_launch(void* const* d_in, const int* in_sizes, int n_in,
                              void* d_out, int out_size)
{
    (void)in_sizes; (void)n_in; (void)out_size;
    const float* x     = (const float*)d_in[0];
    const float* eWih0 = (const float*)d_in[1];
    const float* eWhh0 = (const float*)d_in[2];
    const float* ebih0 = (const float*)d_in[3];
    const float* ebhh0 = (const float*)d_in[4];
    const float* eWih1 = (const float*)d_in[5];
    const float* eWhh1 = (const float*)d_in[6];
    const float* ebih1 = (const float*)d_in[7];
    const float* ebhh1 = (const float*)d_in[8];
    const float* dWih0 = (const float*)d_in[9];
    const float* dWhh0 = (const float*)d_in[10];
    const float* dbih0 = (const float*)d_in[11];
    const float* dbhh0 = (const float*)d_in[12];
    const float* dWih1 = (const float*)d_in[13];
    const float* dWhh1 = (const float*)d_in[14];
    const float* dbih1 = (const float*)d_in[15];
    const float* dbhh1 = (const float*)d_in[16];
    const float* fcW   = (const float*)d_in[17];
    const float* fcb   = (const float*)d_in[18];
    float* out = (float*)d_out;

    float *xgp, *hseqp, *latp, *xgcp;
    cudaGetSymbolAddress((void**)&xgp,   g_xg);
    cudaGetSymbolAddress((void**)&hseqp, g_hseq);
    cudaGetSymbolAddress((void**)&latp,  g_lat);
    cudaGetSymbolAddress((void**)&xgcp,  g_xgc);

    dim3 gbig(TT * BB / 128, GG / 64);  // (1024, 4)
    dim3 gsm(BB / 128, GG / 64);        // (4, 4)
    dim3 gscan(BB / 4);                 // 128 blocks, 4 batch each
    dim3 gfc(TT * BB / 128);            // 1024 blocks

    // Encoder layer 0
    xg_gemm<<<gbig, 256>>>(x, TT * 64, 64, eWih0, ebih0, ebhh0, xgp);
    lstm_scan<0, 0><<<gscan, 256>>>(xgp, eWhh0, hseqp);

    // Encoder layer 1 -> latent
    xg_gemm<<<gbig, 256>>>(hseqp, 64, BB * 64, eWih1, ebih1, ebhh1, xgp);
    lstm_scan<0, 1><<<gscan, 256>>>(xgp, eWhh1, latp);

    // Decoder layer 0 (constant input)
    xg_gemm<<<gsm, 256>>>(latp, 64, 0, dWih0, dbih0, dbhh0, xgcp);
    lstm_scan<1, 0><<<gscan, 256>>>(xgcp, dWhh0, hseqp);

    // Decoder layer 1
    xg_gemm<<<gbig, 256>>>(hseqp, 64, BB * 64, dWih1, dbih1, dbhh1, xgp);
    lstm_scan<0, 0><<<gscan, 256>>>(xgp, dWhh1, hseqp);

    // Output projection
    fc_gemm<<<gfc, 256>>>(hseqp, fcW, fcb, out);
}